// round 1
// baseline (speedup 1.0000x reference)
#include <cuda_runtime.h>
#include <cuda_bf16.h>
#include <math.h>

// Problem constants
#define S 2048        // tokens
#define D 1024        // model dim
#define E 8           // experts
#define M 4096        // ffn dim
#define NSLOT (2*S)   // total assignments (top-2)

// ---------------- device scratch (static, no runtime alloc) ----------------
__device__ float g_H[(size_t)NSLOT * M];     // 67 MB intermediate H
__device__ int   g_cnt[E];
__device__ int   g_off[E + 1];
__device__ int   g_pos[E];
__device__ int   g_slot_tok[NSLOT];
__device__ float g_slot_w[NSLOT];
__device__ int   g_tok_e[S * 2];
__device__ float g_tok_w[S * 2];

// ---------------- kernel 0: zero counters + output ----------------
__global__ void k_init(float* out) {
    int t = blockIdx.x * blockDim.x + threadIdx.x;
    if (t < S * D) out[t] = 0.0f;
    if (t < E) g_cnt[t] = 0;
}

// ---------------- kernel 1: gating (1 warp / token) ----------------
__global__ void k_gate(const float* __restrict__ x,
                       const float* __restrict__ Wgate,
                       const float* __restrict__ bgate) {
    int warp = (blockIdx.x * blockDim.x + threadIdx.x) >> 5;
    int lane = threadIdx.x & 31;
    if (warp >= S) return;
    const float* xr = x + (size_t)warp * D;
    float acc[E];
#pragma unroll
    for (int e = 0; e < E; e++) acc[e] = 0.0f;
    for (int d = lane; d < D; d += 32) {
        float xv = xr[d];
        const float* wr = Wgate + d * E;
#pragma unroll
        for (int e = 0; e < E; e++) acc[e] += xv * wr[e];
    }
#pragma unroll
    for (int e = 0; e < E; e++) {
#pragma unroll
        for (int o = 16; o > 0; o >>= 1)
            acc[e] += __shfl_down_sync(0xffffffffu, acc[e], o);
    }
    if (lane == 0) {
        float l[E];
        float mx = -1e30f;
#pragma unroll
        for (int e = 0; e < E; e++) { l[e] = acc[e] + bgate[e]; mx = fmaxf(mx, l[e]); }
        float ex[E];
#pragma unroll
        for (int e = 0; e < E; e++) ex[e] = expf(l[e] - mx);
        // top-2 (lowest index wins ties, matching jax top_k)
        int i0 = 0;
#pragma unroll
        for (int e = 1; e < E; e++) if (ex[e] > ex[i0]) i0 = e;
        int i1 = (i0 == 0) ? 1 : 0;
#pragma unroll
        for (int e = 0; e < E; e++) if (e != i0 && ex[e] > ex[i1]) i1 = e;
        float w0 = ex[i0], w1 = ex[i1];
        float inv = 1.0f / (w0 + w1);
        w0 *= inv; w1 *= inv;
        g_tok_e[warp * 2 + 0] = i0; g_tok_w[warp * 2 + 0] = w0;
        g_tok_e[warp * 2 + 1] = i1; g_tok_w[warp * 2 + 1] = w1;
        atomicAdd(&g_cnt[i0], 1);
        atomicAdd(&g_cnt[i1], 1);
    }
}

// ---------------- kernel 2: prefix offsets ----------------
__global__ void k_offsets() {
    if (threadIdx.x == 0) {
        int acc = 0;
        g_off[0] = 0;
        for (int e = 0; e < E; e++) {
            acc += g_cnt[e];
            g_off[e + 1] = acc;
            g_pos[e] = g_off[e];
        }
    }
}

// ---------------- kernel 3: scatter tokens into expert-contiguous slots ----
__global__ void k_scatter() {
    int t = blockIdx.x * blockDim.x + threadIdx.x;
    if (t >= S) return;
#pragma unroll
    for (int k = 0; k < 2; k++) {
        int e = g_tok_e[t * 2 + k];
        int p = atomicAdd(&g_pos[e], 1);
        g_slot_tok[p] = t;
        g_slot_w[p] = g_tok_w[t * 2 + k];
    }
}

// ---------------- GEMM tiling ----------------
#define TM 128
#define TN 64
#define TK 16
#define TMP (TM + 4)   // pad to kill STS bank conflicts

// ---------------- kernel 4: H = swish(X@Wg+bg) * (X@W1+b1), grouped ----------
__global__ void __launch_bounds__(256, 2)
k_ff1(const float* __restrict__ x,
      const float* __restrict__ Wg, const float* __restrict__ bg,
      const float* __restrict__ W1, const float* __restrict__ b1) {
    int e = blockIdx.z;
    int base = g_off[e];
    int cnt = g_off[e + 1] - base;
    int row0 = blockIdx.y * TM;
    if (row0 >= cnt) return;
    int col0 = blockIdx.x * TN;

    __shared__ float As[TK][TMP];
    __shared__ float Bg[TK][TN];
    __shared__ float B1[TK][TN];

    int tid = threadIdx.x;
    int tx = tid & 15;        // 0..15 -> 4 cols each
    int ty = tid >> 4;        // 0..15 -> 8 rows each

    // B load indices
    int kk = tid >> 4;        // 0..15
    int cc = (tid & 15) * 4;  // 0..60
    const float* wg_base = Wg + ((size_t)e * D) * M + col0 + cc;
    const float* w1_base = W1 + ((size_t)e * D) * M + col0 + cc;

    float acc_g[8][4], acc_1[8][4];
#pragma unroll
    for (int i = 0; i < 8; i++)
#pragma unroll
        for (int j = 0; j < 4; j++) { acc_g[i][j] = 0.0f; acc_1[i][j] = 0.0f; }

    for (int k0 = 0; k0 < D; k0 += TK) {
        // A tile (gathered tokens), 2048 elems, 2 x float4 per thread
#pragma unroll
        for (int p = 0; p < 2; p++) {
            int f = tid + p * 256;       // 0..511
            int r = f >> 2;              // 0..127
            int kq = (f & 3) * 4;        // 0,4,8,12
            float4 v = make_float4(0.f, 0.f, 0.f, 0.f);
            int gr = row0 + r;
            if (gr < cnt) {
                int tok = g_slot_tok[base + gr];
                v = *(const float4*)&x[(size_t)tok * D + k0 + kq];
            }
            As[kq + 0][r] = v.x;
            As[kq + 1][r] = v.y;
            As[kq + 2][r] = v.z;
            As[kq + 3][r] = v.w;
        }
        // B tiles
        *(float4*)&Bg[kk][cc] = *(const float4*)&wg_base[(size_t)(k0 + kk) * M];
        *(float4*)&B1[kk][cc] = *(const float4*)&w1_base[(size_t)(k0 + kk) * M];
        __syncthreads();

#pragma unroll
        for (int k = 0; k < TK; k++) {
            float4 a0 = *(float4*)&As[k][ty * 8];
            float4 a1 = *(float4*)&As[k][ty * 8 + 4];
            float4 vg = *(float4*)&Bg[k][tx * 4];
            float4 v1 = *(float4*)&B1[k][tx * 4];
            float av[8] = {a0.x, a0.y, a0.z, a0.w, a1.x, a1.y, a1.z, a1.w};
            float gv[4] = {vg.x, vg.y, vg.z, vg.w};
            float ov[4] = {v1.x, v1.y, v1.z, v1.w};
#pragma unroll
            for (int i = 0; i < 8; i++)
#pragma unroll
                for (int j = 0; j < 4; j++) {
                    acc_g[i][j] += av[i] * gv[j];
                    acc_1[i][j] += av[i] * ov[j];
                }
        }
        __syncthreads();
    }

    // epilogue: swish-gate, write H
#pragma unroll
    for (int i = 0; i < 8; i++) {
        int r = row0 + ty * 8 + i;
        if (r >= cnt) continue;
        int slot = base + r;
#pragma unroll
        for (int j = 0; j < 4; j++) {
            int c = col0 + tx * 4 + j;
            float a = acc_g[i][j] + bg[e * M + c];
            float sw = a / (1.0f + expf(-a));        // a * sigmoid(a)
            float h = sw * (acc_1[i][j] + b1[e * M + c]);
            g_H[(size_t)slot * M + c] = h;
        }
    }
}

// ---------------- kernel 5: Y = H@W2 + b2, weighted scatter-add ----------
__global__ void __launch_bounds__(256, 2)
k_ff2(const float* __restrict__ W2, const float* __restrict__ b2,
      float* __restrict__ out) {
    int e = blockIdx.z;
    int base = g_off[e];
    int cnt = g_off[e + 1] - base;
    int row0 = blockIdx.y * TM;
    if (row0 >= cnt) return;
    int col0 = blockIdx.x * TN;

    __shared__ float As[TK][TMP];
    __shared__ float Bs[TK][TN];

    int tid = threadIdx.x;
    int tx = tid & 15;
    int ty = tid >> 4;
    int kk = tid >> 4;
    int cc = (tid & 15) * 4;
    const float* w2_base = W2 + ((size_t)e * M) * D + col0 + cc;

    float acc[8][4];
#pragma unroll
    for (int i = 0; i < 8; i++)
#pragma unroll
        for (int j = 0; j < 4; j++) acc[i][j] = 0.0f;

    for (int k0 = 0; k0 < M; k0 += TK) {
#pragma unroll
        for (int p = 0; p < 2; p++) {
            int f = tid + p * 256;
            int r = f >> 2;
            int kq = (f & 3) * 4;
            float4 v = make_float4(0.f, 0.f, 0.f, 0.f);
            int gr = row0 + r;
            if (gr < cnt) {
                int slot = base + gr;
                v = *(const float4*)&g_H[(size_t)slot * M + k0 + kq];
            }
            As[kq + 0][r] = v.x;
            As[kq + 1][r] = v.y;
            As[kq + 2][r] = v.z;
            As[kq + 3][r] = v.w;
        }
        *(float4*)&Bs[kk][cc] = *(const float4*)&w2_base[(size_t)(k0 + kk) * D];
        __syncthreads();

#pragma unroll
        for (int k = 0; k < TK; k++) {
            float4 a0 = *(float4*)&As[k][ty * 8];
            float4 a1 = *(float4*)&As[k][ty * 8 + 4];
            float4 bv = *(float4*)&Bs[k][tx * 4];
            float av[8] = {a0.x, a0.y, a0.z, a0.w, a1.x, a1.y, a1.z, a1.w};
            float bvv[4] = {bv.x, bv.y, bv.z, bv.w};
#pragma unroll
            for (int i = 0; i < 8; i++)
#pragma unroll
                for (int j = 0; j < 4; j++)
                    acc[i][j] += av[i] * bvv[j];
        }
        __syncthreads();
    }

#pragma unroll
    for (int i = 0; i < 8; i++) {
        int r = row0 + ty * 8 + i;
        if (r >= cnt) continue;
        int slot = base + r;
        int tok = g_slot_tok[slot];
        float w = g_slot_w[slot];
#pragma unroll
        for (int j = 0; j < 4; j++) {
            int c = col0 + tx * 4 + j;
            float y = acc[i][j] + b2[e * D + c];
            atomicAdd(&out[(size_t)tok * D + c], w * y);
        }
    }
}

// ---------------- launch ----------------
extern "C" void kernel_launch(void* const* d_in, const int* in_sizes, int n_in,
                              void* d_out, int out_size) {
    const float* x     = (const float*)d_in[0];
    const float* Wgate = (const float*)d_in[1];
    const float* bgate = (const float*)d_in[2];
    const float* Wg    = (const float*)d_in[3];
    const float* bg    = (const float*)d_in[4];
    const float* W1    = (const float*)d_in[5];
    const float* b1    = (const float*)d_in[6];
    const float* W2    = (const float*)d_in[7];
    const float* b2    = (const float*)d_in[8];
    float* out = (float*)d_out;

    // zero out + counters
    k_init<<<(S * D + 511) / 512, 512>>>(out);
    // gating: 2048 warps = 256 blocks x 8 warps
    k_gate<<<S / 8, 256>>>(x, Wgate, bgate);
    k_offsets<<<1, 32>>>();
    k_scatter<<<(S + 255) / 256, 256>>>();
    // grouped GEMM 1: H
    dim3 g1(M / TN, (S + TM - 1) / TM, E);     // (64, 16, 8), most tiles exit
    k_ff1<<<g1, 256>>>(x, Wg, bg, W1, b1);
    // grouped GEMM 2: combine
    dim3 g2(D / TN, (S + TM - 1) / TM, E);     // (16, 16, 8)
    k_ff2<<<g2, 256>>>(W2, b2, out);
}

// round 6
// speedup vs baseline: 1.3994x; 1.3994x over previous
#include <cuda_runtime.h>
#include <cuda_bf16.h>
#include <math.h>
#include <stdint.h>

// Problem constants
#define S 2048
#define D 1024
#define E 8
#define M 4096
#define NSLOT (2*S)

// ---------------- device scratch ----------------
__device__ __nv_bfloat16 g_H_hi[(size_t)NSLOT * M];
__device__ __nv_bfloat16 g_H_lo[(size_t)NSLOT * M];
__device__ int   g_cnt[E];
__device__ int   g_off[E + 1];
__device__ int   g_pos[E];
__device__ int   g_slot_tok[NSLOT];
__device__ float g_slot_w[NSLOT];
__device__ int   g_tok_e[S * 2];
__device__ float g_tok_w[S * 2];

// ---------------- helpers ----------------
__device__ __forceinline__ uint32_t smem_u32(const void* p) {
    uint32_t a;
    asm("{ .reg .u64 t; cvta.to.shared.u64 t, %1; cvt.u32.u64 %0, t; }" : "=r"(a) : "l"(p));
    return a;
}

#define LDSM4(r0, r1, r2, r3, addr) \
    asm volatile("ldmatrix.sync.aligned.m8n8.x4.shared.b16 {%0,%1,%2,%3}, [%4];" \
        : "=r"(r0), "=r"(r1), "=r"(r2), "=r"(r3) : "r"(addr))

#define MMA16816(c, a0, a1, a2, a3, b0, b1) \
    asm volatile("mma.sync.aligned.m16n8k16.row.col.f32.bf16.bf16.f32 " \
        "{%0,%1,%2,%3}, {%4,%5,%6,%7}, {%8,%9}, {%0,%1,%2,%3};" \
        : "+f"((c)[0]), "+f"((c)[1]), "+f"((c)[2]), "+f"((c)[3]) \
        : "r"(a0), "r"(a1), "r"(a2), "r"(a3), "r"(b0), "r"(b1))

// Split fp32 pair -> packed bf16x2 hi and lo
__device__ __forceinline__ void split2(float a, float b, uint32_t& hi, uint32_t& lo) {
    __nv_bfloat16 ah = __float2bfloat16(a);
    __nv_bfloat16 bh = __float2bfloat16(b);
    __nv_bfloat162 h2; h2.x = ah; h2.y = bh;
    __nv_bfloat162 l2 = __floats2bfloat162_rn(a - __bfloat162float(ah),
                                              b - __bfloat162float(bh));
    hi = *(uint32_t*)&h2;
    lo = *(uint32_t*)&l2;
}

// ---------------- kernel 0: zero output + counters ----------------
__global__ void k_init(float* out) {
    int t = blockIdx.x * blockDim.x + threadIdx.x;
    if (t < S * D) out[t] = 0.0f;
    if (t < E) g_cnt[t] = 0;
}

// ---------------- kernel 1: gating (1 warp / token) ----------------
__global__ void k_gate(const float* __restrict__ x,
                       const float* __restrict__ Wgate,
                       const float* __restrict__ bgate) {
    int warp = (blockIdx.x * blockDim.x + threadIdx.x) >> 5;
    int lane = threadIdx.x & 31;
    if (warp >= S) return;
    const float* xr = x + (size_t)warp * D;
    float acc[E];
#pragma unroll
    for (int e = 0; e < E; e++) acc[e] = 0.0f;
    for (int d = lane; d < D; d += 32) {
        float xv = xr[d];
        const float* wr = Wgate + d * E;
#pragma unroll
        for (int e = 0; e < E; e++) acc[e] += xv * wr[e];
    }
#pragma unroll
    for (int e = 0; e < E; e++) {
#pragma unroll
        for (int o = 16; o > 0; o >>= 1)
            acc[e] += __shfl_down_sync(0xffffffffu, acc[e], o);
    }
    if (lane == 0) {
        float l[E];
        float mx = -1e30f;
#pragma unroll
        for (int e = 0; e < E; e++) { l[e] = acc[e] + bgate[e]; mx = fmaxf(mx, l[e]); }
        float ex[E];
#pragma unroll
        for (int e = 0; e < E; e++) ex[e] = expf(l[e] - mx);
        int i0 = 0;
#pragma unroll
        for (int e = 1; e < E; e++) if (ex[e] > ex[i0]) i0 = e;
        int i1 = (i0 == 0) ? 1 : 0;
#pragma unroll
        for (int e = 0; e < E; e++) if (e != i0 && ex[e] > ex[i1]) i1 = e;
        float w0 = ex[i0], w1 = ex[i1];
        float inv = 1.0f / (w0 + w1);
        w0 *= inv; w1 *= inv;
        g_tok_e[warp * 2 + 0] = i0; g_tok_w[warp * 2 + 0] = w0;
        g_tok_e[warp * 2 + 1] = i1; g_tok_w[warp * 2 + 1] = w1;
        atomicAdd(&g_cnt[i0], 1);
        atomicAdd(&g_cnt[i1], 1);
    }
}

// ---------------- kernel 2: prefix offsets ----------------
__global__ void k_offsets() {
    if (threadIdx.x == 0) {
        int acc = 0;
        g_off[0] = 0;
        for (int e = 0; e < E; e++) {
            acc += g_cnt[e];
            g_off[e + 1] = acc;
            g_pos[e] = g_off[e];
        }
    }
}

// ---------------- kernel 3: scatter ----------------
__global__ void k_scatter() {
    int t = blockIdx.x * blockDim.x + threadIdx.x;
    if (t >= S) return;
#pragma unroll
    for (int k = 0; k < 2; k++) {
        int e = g_tok_e[t * 2 + k];
        int p = atomicAdd(&g_pos[e], 1);
        g_slot_tok[p] = t;
        g_slot_w[p] = g_tok_w[t * 2 + k];
    }
}

// ---------------- tiling constants ----------------
#define ASTRIDE 40                 // smem row stride in bf16 elems (80 B, 16B-aligned rows)
#define TILE_B  (128 * ASTRIDE * 2)  // 10240 bytes per 128x32 tile

// ff1 smem offsets (bytes)
#define F1_ASH  0
#define F1_ASL  (1 * TILE_B)
#define F1_BGH  (2 * TILE_B)
#define F1_BGL  (3 * TILE_B)
#define F1_BUH  (4 * TILE_B)
#define F1_BUL  (5 * TILE_B)
#define F1_TOK  (6 * TILE_B)
#define F1_SMEM (F1_TOK + 512)     // 61952

// ---------------- kernel 4: ff1  H = swish(X@Wg+bg) * (X@W1+b1) ----------------
__global__ void __launch_bounds__(256)
k_ff1(const float* __restrict__ x,
      const float* __restrict__ Wg, const float* __restrict__ bg,
      const float* __restrict__ W1, const float* __restrict__ b1) {
    extern __shared__ char smem[];
    const int e = blockIdx.z;
    const int base = g_off[e];
    const int cnt = g_off[e + 1] - base;
    const int row0 = blockIdx.x * 128;
    if (row0 >= cnt) return;
    const int col0 = blockIdx.y * 128;
    const int tid = threadIdx.x;
    const int wid = tid >> 5, lane = tid & 31;
    const int warp_m = wid >> 2, warp_n = wid & 3;
    const uint32_t sb = smem_u32(smem);

    // token list for this row tile
    if (tid < 128) {
        int gr = row0 + tid;
        ((int*)(smem + F1_TOK))[tid] = (gr < cnt) ? g_slot_tok[base + gr] : -1;
    }
    const int* s_tok = (const int*)(smem + F1_TOK);

    const float* Wg_c = Wg + (size_t)e * D * M + col0;
    const float* W1_c = W1 + (size_t)e * D * M + col0;

    // per-lane ldmatrix address components (rows 16B-aligned: ASTRIDE*2 = 80B)
    const uint32_t a_off = sb + (uint32_t)(((warp_m * 64 + (lane & 15)) * ASTRIDE
                                            + (lane >> 4) * 8) * 2);
    const uint32_t b_off = sb + (uint32_t)(((warp_n * 32 + (lane & 7) + ((lane >> 4) * 8)) * ASTRIDE
                                            + ((lane >> 3) & 1) * 8) * 2);

    float cg[4][4][4], cu[4][4][4];
#pragma unroll
    for (int i = 0; i < 4; i++)
#pragma unroll
        for (int j = 0; j < 4; j++)
#pragma unroll
            for (int q = 0; q < 4; q++) { cg[i][j][q] = 0.0f; cu[i][j][q] = 0.0f; }

    for (int k0 = 0; k0 < D; k0 += 32) {
        __syncthreads();   // protect previous iter's ldmatrix reads
        // ---- A tile: gathered tokens, fp32 -> bf16 hi/lo ----
#pragma unroll
        for (int p = 0; p < 4; p++) {
            int idx = p * 256 + tid;
            int r = idx >> 3, kq = (idx & 7) * 4;
            int tok = s_tok[r];
            float4 v = make_float4(0.f, 0.f, 0.f, 0.f);
            if (tok >= 0) v = *(const float4*)(x + (size_t)tok * D + k0 + kq);
            uint32_t h0, l0, h1, l1;
            split2(v.x, v.y, h0, l0);
            split2(v.z, v.w, h1, l1);
            int bo = (r * ASTRIDE + kq) * 2;
            *(uint32_t*)(smem + F1_ASH + bo)     = h0;
            *(uint32_t*)(smem + F1_ASH + bo + 4) = h1;
            *(uint32_t*)(smem + F1_ASL + bo)     = l0;
            *(uint32_t*)(smem + F1_ASL + bo + 4) = l1;
        }
        // ---- B tiles: transpose-convert Wg/W1 [k][n] -> [n][k] hi/lo ----
#pragma unroll
        for (int p = 0; p < 16; p++) {
            int idx = p * 256 + tid;
            int kk = idx >> 7, n = idx & 127;
            size_t ga = (size_t)(k0 + kk) * M + n;
            float gv = Wg_c[ga];
            float uv = W1_c[ga];
            __nv_bfloat16 gh = __float2bfloat16(gv);
            __nv_bfloat16 gl = __float2bfloat16(gv - __bfloat162float(gh));
            __nv_bfloat16 uh = __float2bfloat16(uv);
            __nv_bfloat16 ul = __float2bfloat16(uv - __bfloat162float(uh));
            int bo = (n * ASTRIDE + kk) * 2;
            *(__nv_bfloat16*)(smem + F1_BGH + bo) = gh;
            *(__nv_bfloat16*)(smem + F1_BGL + bo) = gl;
            *(__nv_bfloat16*)(smem + F1_BUH + bo) = uh;
            *(__nv_bfloat16*)(smem + F1_BUL + bo) = ul;
        }
        __syncthreads();

#pragma unroll
        for (int ks = 0; ks < 2; ks++) {
            const uint32_t kso = (uint32_t)(ks * 16 * 2);
            uint32_t ah[4][4], al[4][4];
#pragma unroll
            for (int mt = 0; mt < 4; mt++) {
                uint32_t ad = a_off + (uint32_t)(mt * 16 * ASTRIDE * 2) + kso;
                LDSM4(ah[mt][0], ah[mt][1], ah[mt][2], ah[mt][3], ad + F1_ASH);
                LDSM4(al[mt][0], al[mt][1], al[mt][2], al[mt][3], ad + F1_ASL);
            }
            uint32_t bgh[4][2], bgl[4][2], buh[4][2], bul[4][2];
#pragma unroll
            for (int nt2 = 0; nt2 < 2; nt2++) {
                uint32_t bd = b_off + (uint32_t)(nt2 * 16 * ASTRIDE * 2) + kso;
                LDSM4(bgh[2*nt2][0], bgh[2*nt2][1], bgh[2*nt2+1][0], bgh[2*nt2+1][1], bd + F1_BGH);
                LDSM4(bgl[2*nt2][0], bgl[2*nt2][1], bgl[2*nt2+1][0], bgl[2*nt2+1][1], bd + F1_BGL);
                LDSM4(buh[2*nt2][0], buh[2*nt2][1], buh[2*nt2+1][0], buh[2*nt2+1][1], bd + F1_BUH);
                LDSM4(bul[2*nt2][0], bul[2*nt2][1], bul[2*nt2+1][0], bul[2*nt2+1][1], bd + F1_BUL);
            }
#pragma unroll
            for (int mt = 0; mt < 4; mt++) {
#pragma unroll
                for (int nt = 0; nt < 4; nt++) {
                    MMA16816(cg[mt][nt], ah[mt][0], ah[mt][1], ah[mt][2], ah[mt][3], bgh[nt][0], bgh[nt][1]);
                    MMA16816(cg[mt][nt], ah[mt][0], ah[mt][1], ah[mt][2], ah[mt][3], bgl[nt][0], bgl[nt][1]);
                    MMA16816(cg[mt][nt], al[mt][0], al[mt][1], al[mt][2], al[mt][3], bgh[nt][0], bgh[nt][1]);
                    MMA16816(cu[mt][nt], ah[mt][0], ah[mt][1], ah[mt][2], ah[mt][3], buh[nt][0], buh[nt][1]);
                    MMA16816(cu[mt][nt], ah[mt][0], ah[mt][1], ah[mt][2], ah[mt][3], bul[nt][0], bul[nt][1]);
                    MMA16816(cu[mt][nt], al[mt][0], al[mt][1], al[mt][2], al[mt][3], buh[nt][0], buh[nt][1]);
                }
            }
        }
    }

    // ---- epilogue: swish-gate, write H as bf16 hi/lo pairs ----
    const float* bg_e = bg + e * M;
    const float* b1_e = b1 + e * M;
    uint32_t* Hh32 = (uint32_t*)g_H_hi;
    uint32_t* Hl32 = (uint32_t*)g_H_lo;
#pragma unroll
    for (int mt = 0; mt < 4; mt++) {
#pragma unroll
        for (int nt = 0; nt < 4; nt++) {
            int r_base = row0 + warp_m * 64 + mt * 16 + (lane >> 2);
            int c = col0 + warp_n * 32 + nt * 8 + (lane & 3) * 2;
#pragma unroll
            for (int hh = 0; hh < 2; hh++) {
                int r = r_base + hh * 8;
                if (r < cnt) {
                    float a0 = cg[mt][nt][2*hh]   + bg_e[c];
                    float a1 = cg[mt][nt][2*hh+1] + bg_e[c + 1];
                    float u0 = cu[mt][nt][2*hh]   + b1_e[c];
                    float u1 = cu[mt][nt][2*hh+1] + b1_e[c + 1];
                    float h0 = (a0 / (1.0f + __expf(-a0))) * u0;
                    float h1 = (a1 / (1.0f + __expf(-a1))) * u1;
                    uint32_t hu, lu;
                    split2(h0, h1, hu, lu);
                    size_t o = ((size_t)(base + r) * M + c) >> 1;
                    Hh32[o] = hu;
                    Hl32[o] = lu;
                }
            }
        }
    }
}

// ff2 smem offsets (bytes), static shared
#define F2_ASH  0
#define F2_ASL  (1 * TILE_B)
#define F2_BH   (2 * TILE_B)
#define F2_BL   (3 * TILE_B)
#define F2_SMEM (4 * TILE_B)       // 40960

// ---------------- kernel 5: ff2  Y = H@W2 + b2, weighted combine ----------------
__global__ void __launch_bounds__(256)
k_ff2(const float* __restrict__ W2, const float* __restrict__ b2,
      float* __restrict__ out) {
    __shared__ __align__(16) char smem[F2_SMEM];
    const int e = blockIdx.z;
    const int base = g_off[e];
    const int cnt = g_off[e + 1] - base;
    const int row0 = blockIdx.x * 128;
    if (row0 >= cnt) return;
    const int col0 = blockIdx.y * 128;
    const int tid = threadIdx.x;
    const int wid = tid >> 5, lane = tid & 31;
    const int warp_m = wid >> 2, warp_n = wid & 3;
    const uint32_t sb = smem_u32(smem);

    const float* W2_c = W2 + (size_t)e * M * D + col0;
    const uint32_t* Hh32 = (const uint32_t*)g_H_hi;
    const uint32_t* Hl32 = (const uint32_t*)g_H_lo;

    const uint32_t a_off = sb + (uint32_t)(((warp_m * 64 + (lane & 15)) * ASTRIDE
                                            + (lane >> 4) * 8) * 2);
    const uint32_t b_off = sb + (uint32_t)(((warp_n * 32 + (lane & 7) + ((lane >> 4) * 8)) * ASTRIDE
                                            + ((lane >> 3) & 1) * 8) * 2);

    float cc[4][4][4];
#pragma unroll
    for (int i = 0; i < 4; i++)
#pragma unroll
        for (int j = 0; j < 4; j++)
#pragma unroll
            for (int q = 0; q < 4; q++) cc[i][j][q] = 0.0f;

    for (int k0 = 0; k0 < M; k0 += 32) {
        __syncthreads();
        // ---- A tile: H rows (already bf16 hi/lo) ----
#pragma unroll
        for (int p = 0; p < 8; p++) {
            int idx = p * 256 + tid;
            int r = idx >> 4, ku = idx & 15;
            int gr = row0 + r;
            uint32_t hv = 0, lv = 0;
            if (gr < cnt) {
                size_t o = (size_t)(base + gr) * (M / 2) + (k0 >> 1) + ku;
                hv = Hh32[o];
                lv = Hl32[o];
            }
            int bo = r * (ASTRIDE * 2) + ku * 4;
            *(uint32_t*)(smem + F2_ASH + bo) = hv;
            *(uint32_t*)(smem + F2_ASL + bo) = lv;
        }
        // ---- B tile: transpose-convert W2 [m][d] -> [d][m] hi/lo ----
#pragma unroll
        for (int p = 0; p < 16; p++) {
            int idx = p * 256 + tid;
            int kk = idx >> 7, n = idx & 127;
            float wv = W2_c[(size_t)(k0 + kk) * D + n];
            __nv_bfloat16 wh = __float2bfloat16(wv);
            __nv_bfloat16 wl = __float2bfloat16(wv - __bfloat162float(wh));
            int bo = (n * ASTRIDE + kk) * 2;
            *(__nv_bfloat16*)(smem + F2_BH + bo) = wh;
            *(__nv_bfloat16*)(smem + F2_BL + bo) = wl;
        }
        __syncthreads();

#pragma unroll
        for (int ks = 0; ks < 2; ks++) {
            const uint32_t kso = (uint32_t)(ks * 16 * 2);
            uint32_t ah[4][4], al[4][4];
#pragma unroll
            for (int mt = 0; mt < 4; mt++) {
                uint32_t ad = a_off + (uint32_t)(mt * 16 * ASTRIDE * 2) + kso;
                LDSM4(ah[mt][0], ah[mt][1], ah[mt][2], ah[mt][3], ad + F2_ASH);
                LDSM4(al[mt][0], al[mt][1], al[mt][2], al[mt][3], ad + F2_ASL);
            }
            uint32_t bh[4][2], bl[4][2];
#pragma unroll
            for (int nt2 = 0; nt2 < 2; nt2++) {
                uint32_t bd = b_off + (uint32_t)(nt2 * 16 * ASTRIDE * 2) + kso;
                LDSM4(bh[2*nt2][0], bh[2*nt2][1], bh[2*nt2+1][0], bh[2*nt2+1][1], bd + F2_BH);
                LDSM4(bl[2*nt2][0], bl[2*nt2][1], bl[2*nt2+1][0], bl[2*nt2+1][1], bd + F2_BL);
            }
#pragma unroll
            for (int mt = 0; mt < 4; mt++) {
#pragma unroll
                for (int nt = 0; nt < 4; nt++) {
                    MMA16816(cc[mt][nt], ah[mt][0], ah[mt][1], ah[mt][2], ah[mt][3], bh[nt][0], bh[nt][1]);
                    MMA16816(cc[mt][nt], ah[mt][0], ah[mt][1], ah[mt][2], ah[mt][3], bl[nt][0], bl[nt][1]);
                    MMA16816(cc[mt][nt], al[mt][0], al[mt][1], al[mt][2], al[mt][3], bh[nt][0], bh[nt][1]);
                }
            }
        }
    }

    // ---- epilogue: bias + weighted atomic combine ----
    const float* b2_e = b2 + e * D;
#pragma unroll
    for (int mt = 0; mt < 4; mt++) {
#pragma unroll
        for (int nt = 0; nt < 4; nt++) {
            int r_base = row0 + warp_m * 64 + mt * 16 + (lane >> 2);
            int c = col0 + warp_n * 32 + nt * 8 + (lane & 3) * 2;
#pragma unroll
            for (int hh = 0; hh < 2; hh++) {
                int r = r_base + hh * 8;
                if (r < cnt) {
                    int slot = base + r;
                    int tok = g_slot_tok[slot];
                    float w = g_slot_w[slot];
                    float y0 = cc[mt][nt][2*hh]   + b2_e[c];
                    float y1 = cc[mt][nt][2*hh+1] + b2_e[c + 1];
                    float* op = out + (size_t)tok * D + c;
                    atomicAdd(op,     w * y0);
                    atomicAdd(op + 1, w * y1);
                }
            }
        }
    }
}

// ---------------- launch ----------------
extern "C" void kernel_launch(void* const* d_in, const int* in_sizes, int n_in,
                              void* d_out, int out_size) {
    const float* x     = (const float*)d_in[0];
    const float* Wgate = (const float*)d_in[1];
    const float* bgate = (const float*)d_in[2];
    const float* Wg    = (const float*)d_in[3];
    const float* bg    = (const float*)d_in[4];
    const float* W1    = (const float*)d_in[5];
    const float* b1    = (const float*)d_in[6];
    const float* W2    = (const float*)d_in[7];
    const float* b2    = (const float*)d_in[8];
    float* out = (float*)d_out;

    cudaFuncSetAttribute(k_ff1, cudaFuncAttributeMaxDynamicSharedMemorySize, F1_SMEM);

    k_init<<<(S * D + 511) / 512, 512>>>(out);
    k_gate<<<S / 8, 256>>>(x, Wgate, bgate);
    k_offsets<<<1, 32>>>();
    k_scatter<<<(S + 255) / 256, 256>>>();

    dim3 g1(NSLOT / 128, M / 128, E);   // (32, 32, 8)
    k_ff1<<<g1, 256, F1_SMEM>>>(x, Wg, bg, W1, b1);
    dim3 g2(NSLOT / 128, D / 128, E);   // (32, 8, 8)
    k_ff2<<<g2, 256>>>(W2, b2, out);
}

// round 10
// speedup vs baseline: 2.0192x; 1.4428x over previous
#include <cuda_runtime.h>
#include <cuda_bf16.h>
#include <math.h>
#include <stdint.h>

// Problem constants
#define S 2048
#define D 1024
#define E 8
#define M 4096
#define NSLOT (2*S)

// ---------------- device scratch (bf16 hi/lo planes) ----------------
__device__ __nv_bfloat16 g_x_hi[(size_t)S * D];
__device__ __nv_bfloat16 g_x_lo[(size_t)S * D];
__device__ __nv_bfloat16 g_Wgt_hi[(size_t)E * M * D];   // [e][n=M][k=D]
__device__ __nv_bfloat16 g_Wgt_lo[(size_t)E * M * D];
__device__ __nv_bfloat16 g_W1t_hi[(size_t)E * M * D];
__device__ __nv_bfloat16 g_W1t_lo[(size_t)E * M * D];
__device__ __nv_bfloat16 g_W2t_hi[(size_t)E * D * M];   // [e][n=D][k=M]
__device__ __nv_bfloat16 g_W2t_lo[(size_t)E * D * M];
__device__ __nv_bfloat16 g_H_hi[(size_t)NSLOT * M];
__device__ __nv_bfloat16 g_H_lo[(size_t)NSLOT * M];
__device__ int   g_cnt[E];
__device__ int   g_off[E + 1];
__device__ int   g_pos[E];
__device__ int   g_slot_tok[NSLOT];
__device__ float g_slot_w[NSLOT];
__device__ int   g_tok_e[S * 2];
__device__ float g_tok_w[S * 2];

// ---------------- helpers ----------------
__device__ __forceinline__ uint32_t smem_u32(const void* p) {
    uint32_t a;
    asm("{ .reg .u64 t; cvta.to.shared.u64 t, %1; cvt.u32.u64 %0, t; }" : "=r"(a) : "l"(p));
    return a;
}

#define LDSM4(r0, r1, r2, r3, addr) \
    asm volatile("ldmatrix.sync.aligned.m8n8.x4.shared.b16 {%0,%1,%2,%3}, [%4];" \
        : "=r"(r0), "=r"(r1), "=r"(r2), "=r"(r3) : "r"(addr))

#define MMA16816(c, a0, a1, a2, a3, b0, b1) \
    asm volatile("mma.sync.aligned.m16n8k16.row.col.f32.bf16.bf16.f32 " \
        "{%0,%1,%2,%3}, {%4,%5,%6,%7}, {%8,%9}, {%0,%1,%2,%3};" \
        : "+f"((c)[0]), "+f"((c)[1]), "+f"((c)[2]), "+f"((c)[3]) \
        : "r"(a0), "r"(a1), "r"(a2), "r"(a3), "r"(b0), "r"(b1))

// Plain 16B cp.async
__device__ __forceinline__ void cpa16(uint32_t dst, const void* src) {
    asm volatile("cp.async.cg.shared.global [%0], [%1], 16;"
                 :: "r"(dst), "l"(src));
}
#define CPCOMMIT() asm volatile("cp.async.commit_group;")
#define CPWAIT(n)  asm volatile("cp.async.wait_group %0;" :: "n"(n))

// Split fp32 pair -> packed bf16x2 hi and lo
__device__ __forceinline__ void split2(float a, float b, uint32_t& hi, uint32_t& lo) {
    __nv_bfloat16 ah = __float2bfloat16(a);
    __nv_bfloat16 bh = __float2bfloat16(b);
    __nv_bfloat162 h2; h2.x = ah; h2.y = bh;
    __nv_bfloat162 l2 = __floats2bfloat162_rn(a - __bfloat162float(ah),
                                              b - __bfloat162float(bh));
    hi = *(uint32_t*)&h2;
    lo = *(uint32_t*)&l2;
}

// ---------------- kernel 0: zero output + counters ----------------
__global__ void k_init(float* out) {
    int t = blockIdx.x * blockDim.x + threadIdx.x;
    if (t < S * D) out[t] = 0.0f;
    if (t < E) g_cnt[t] = 0;
}

// ---------------- kernel 1: gating (1 warp / token) ----------------
__global__ void k_gate(const float* __restrict__ x,
                       const float* __restrict__ Wgate,
                       const float* __restrict__ bgate) {
    int warp = (blockIdx.x * blockDim.x + threadIdx.x) >> 5;
    int lane = threadIdx.x & 31;
    if (warp >= S) return;
    const float* xr = x + (size_t)warp * D;
    float acc[E];
#pragma unroll
    for (int e = 0; e < E; e++) acc[e] = 0.0f;
    for (int d = lane; d < D; d += 32) {
        float xv = xr[d];
        const float* wr = Wgate + d * E;
#pragma unroll
        for (int e = 0; e < E; e++) acc[e] += xv * wr[e];
    }
#pragma unroll
    for (int e = 0; e < E; e++) {
#pragma unroll
        for (int o = 16; o > 0; o >>= 1)
            acc[e] += __shfl_down_sync(0xffffffffu, acc[e], o);
    }
    if (lane == 0) {
        float l[E];
        float mx = -1e30f;
#pragma unroll
        for (int e = 0; e < E; e++) { l[e] = acc[e] + bgate[e]; mx = fmaxf(mx, l[e]); }
        float ex[E];
#pragma unroll
        for (int e = 0; e < E; e++) ex[e] = expf(l[e] - mx);
        int i0 = 0;
#pragma unroll
        for (int e = 1; e < E; e++) if (ex[e] > ex[i0]) i0 = e;
        int i1 = (i0 == 0) ? 1 : 0;
#pragma unroll
        for (int e = 0; e < E; e++) if (e != i0 && ex[e] > ex[i1]) i1 = e;
        float w0 = ex[i0], w1 = ex[i1];
        float inv = 1.0f / (w0 + w1);
        w0 *= inv; w1 *= inv;
        g_tok_e[warp * 2 + 0] = i0; g_tok_w[warp * 2 + 0] = w0;
        g_tok_e[warp * 2 + 1] = i1; g_tok_w[warp * 2 + 1] = w1;
        atomicAdd(&g_cnt[i0], 1);
        atomicAdd(&g_cnt[i1], 1);
    }
}

// ---------------- kernel 2: prefix offsets ----------------
__global__ void k_offsets() {
    if (threadIdx.x == 0) {
        int acc = 0;
        g_off[0] = 0;
        for (int e = 0; e < E; e++) {
            acc += g_cnt[e];
            g_off[e + 1] = acc;
            g_pos[e] = g_off[e];
        }
    }
}

// ---------------- kernel 3: scatter ----------------
__global__ void k_scatter() {
    int t = blockIdx.x * blockDim.x + threadIdx.x;
    if (t >= S) return;
#pragma unroll
    for (int k = 0; k < 2; k++) {
        int e = g_tok_e[t * 2 + k];
        int p = atomicAdd(&g_pos[e], 1);
        g_slot_tok[p] = t;
        g_slot_w[p] = g_tok_w[t * 2 + k];
    }
}

// ---------------- prep: split x (device-code symbol refs — correct) ----------------
__global__ void k_xsplit(const float* __restrict__ x) {
    int i = blockIdx.x * blockDim.x + threadIdx.x;
    if (i >= S * D / 2) return;
    float2 v = ((const float2*)x)[i];
    uint32_t h, l;
    split2(v.x, v.y, h, l);
    ((uint32_t*)g_x_hi)[i] = h;
    ((uint32_t*)g_x_lo)[i] = l;
}

// ---------------- prep: transpose + split weights  in[K][N] -> out[N][K] ----------
// FIX: output plane selected IN DEVICE CODE (passing __device__ symbols as host-side
// kernel args passes the host shadow address -> writes landed in host memory via ATS).
__global__ void k_tsplit(const float* __restrict__ in, int which, int K, int N) {
    __nv_bfloat16 *oh, *ol;
    if (which == 0)      { oh = g_Wgt_hi; ol = g_Wgt_lo; }
    else if (which == 1) { oh = g_W1t_hi; ol = g_W1t_lo; }
    else                 { oh = g_W2t_hi; ol = g_W2t_lo; }
    __shared__ float t[32][33];
    const size_t eo = (size_t)blockIdx.z * K * N;
    in += eo; oh += eo; ol += eo;
    int n0 = blockIdx.x * 32, k0 = blockIdx.y * 32;
    int tx = threadIdx.x, ty = threadIdx.y;   // (32, 8)
#pragma unroll
    for (int i = 0; i < 4; i++)
        t[ty + 8 * i][tx] = in[(size_t)(k0 + ty + 8 * i) * N + n0 + tx];
    __syncthreads();
#pragma unroll
    for (int i = 0; i < 4; i++) {
        float v = t[tx][ty + 8 * i];
        __nv_bfloat16 h = __float2bfloat16(v);
        __nv_bfloat16 l = __float2bfloat16(v - __bfloat162float(h));
        size_t o = (size_t)(n0 + ty + 8 * i) * K + k0 + tx;
        oh[o] = h;
        ol[o] = l;
    }
}

// ---------------- GEMM tiling ----------------
#define AS 40                       // smem row stride, bf16 elems (80 B)
#define ROWB (AS * 2)               // 80
#define TILEB (128 * ROWB)          // 10240 bytes per 128x32 plane

// ff1: stage = 6 planes (A hi/lo, G hi/lo, U hi/lo), double buffered
#define F1_STG  (6 * TILEB)         // 61440
#define F1_SMEM (2 * F1_STG + 512)  // 123392

__device__ __forceinline__ void ff1_load(uint32_t sb, int stage, int k0,
                                         int tid, const int* s_tok,
                                         int e, int col0) {
    uint32_t st = sb + stage * F1_STG;
    int ch = tid & 3;
    // A: x hi/lo gathered rows (invalid rows clamped to token 0; discarded in epilogue)
#pragma unroll
    for (int p = 0; p < 4; p++) {
        int r = (((p & 1) << 8) + tid) >> 2;
        const __nv_bfloat16* xs = (p >> 1) ? g_x_lo : g_x_hi;
        int tok = s_tok[r];
        if (tok < 0) tok = 0;
        const void* src = xs + (size_t)tok * D + k0 + ch * 8;
        cpa16(st + (p >> 1) * TILEB + r * ROWB + ch * 16, src);
    }
    // B: Wg/W1 transposed planes [n][k]
#pragma unroll
    for (int p = 0; p < 8; p++) {
        int r = (((p & 1) << 8) + tid) >> 2;
        const __nv_bfloat16* ws = (p >> 1) == 0 ? g_Wgt_hi
                                : (p >> 1) == 1 ? g_Wgt_lo
                                : (p >> 1) == 2 ? g_W1t_hi : g_W1t_lo;
        const void* src = ws + ((size_t)e * M + col0 + r) * (size_t)D + k0 + ch * 8;
        cpa16(st + (2 + (p >> 1)) * TILEB + r * ROWB + ch * 16, src);
    }
}

// ---------------- kernel 4: ff1  H = swish(X@Wg+bg) * (X@W1+b1) ----------------
__global__ void __launch_bounds__(256)
k_ff1(const float* __restrict__ bg, const float* __restrict__ b1) {
    extern __shared__ char smem[];
    const int e = blockIdx.z;
    const int base = g_off[e];
    const int cnt = g_off[e + 1] - base;
    const int row0 = blockIdx.x * 128;
    if (row0 >= cnt) return;
    const int col0 = blockIdx.y * 128;
    const int tid = threadIdx.x;
    const int wid = tid >> 5, lane = tid & 31;
    const int warp_m = wid >> 2, warp_n = wid & 3;
    const uint32_t sb = smem_u32(smem);

    int* s_tok = (int*)(smem + 2 * F1_STG);
    if (tid < 128) {
        int gr = row0 + tid;
        s_tok[tid] = (gr < cnt) ? g_slot_tok[base + gr] : -1;
    }
    __syncthreads();

    const uint32_t a_rel = (uint32_t)(((warp_m * 64 + (lane & 15)) * AS + (lane >> 4) * 8) * 2);
    const uint32_t b_rel = (uint32_t)(((warp_n * 32 + (lane & 7) + ((lane >> 4) * 8)) * AS
                                      + ((lane >> 3) & 1) * 8) * 2);

    float cg[4][4][4], cu[4][4][4];
#pragma unroll
    for (int i = 0; i < 4; i++)
#pragma unroll
        for (int j = 0; j < 4; j++)
#pragma unroll
            for (int q = 0; q < 4; q++) { cg[i][j][q] = 0.0f; cu[i][j][q] = 0.0f; }

    ff1_load(sb, 0, 0, tid, s_tok, e, col0);
    CPCOMMIT();

    for (int it = 0; it < 32; it++) {
        if (it + 1 < 32) {
            ff1_load(sb, (it + 1) & 1, (it + 1) * 32, tid, s_tok, e, col0);
            CPCOMMIT();
            CPWAIT(1);
        } else {
            CPWAIT(0);
        }
        __syncthreads();
        uint32_t st = sb + (it & 1) * F1_STG;
#pragma unroll
        for (int ks = 0; ks < 2; ks++) {
            const uint32_t kso = (uint32_t)(ks * 16 * 2);
            uint32_t ah[4][4], al[4][4];
#pragma unroll
            for (int mt = 0; mt < 4; mt++) {
                uint32_t ad = st + a_rel + (uint32_t)(mt * 16 * ROWB) + kso;
                LDSM4(ah[mt][0], ah[mt][1], ah[mt][2], ah[mt][3], ad);
                LDSM4(al[mt][0], al[mt][1], al[mt][2], al[mt][3], ad + TILEB);
            }
            uint32_t bgh[4][2], bgl[4][2], buh[4][2], bul[4][2];
#pragma unroll
            for (int nt2 = 0; nt2 < 2; nt2++) {
                uint32_t bd = st + b_rel + (uint32_t)(nt2 * 16 * ROWB) + kso;
                LDSM4(bgh[2*nt2][0], bgh[2*nt2][1], bgh[2*nt2+1][0], bgh[2*nt2+1][1], bd + 2 * TILEB);
                LDSM4(bgl[2*nt2][0], bgl[2*nt2][1], bgl[2*nt2+1][0], bgl[2*nt2+1][1], bd + 3 * TILEB);
                LDSM4(buh[2*nt2][0], buh[2*nt2][1], buh[2*nt2+1][0], buh[2*nt2+1][1], bd + 4 * TILEB);
                LDSM4(bul[2*nt2][0], bul[2*nt2][1], bul[2*nt2+1][0], bul[2*nt2+1][1], bd + 5 * TILEB);
            }
#pragma unroll
            for (int mt = 0; mt < 4; mt++) {
#pragma unroll
                for (int nt = 0; nt < 4; nt++) {
                    MMA16816(cg[mt][nt], ah[mt][0], ah[mt][1], ah[mt][2], ah[mt][3], bgh[nt][0], bgh[nt][1]);
                    MMA16816(cg[mt][nt], ah[mt][0], ah[mt][1], ah[mt][2], ah[mt][3], bgl[nt][0], bgl[nt][1]);
                    MMA16816(cg[mt][nt], al[mt][0], al[mt][1], al[mt][2], al[mt][3], bgh[nt][0], bgh[nt][1]);
                    MMA16816(cu[mt][nt], ah[mt][0], ah[mt][1], ah[mt][2], ah[mt][3], buh[nt][0], buh[nt][1]);
                    MMA16816(cu[mt][nt], ah[mt][0], ah[mt][1], ah[mt][2], ah[mt][3], bul[nt][0], bul[nt][1]);
                    MMA16816(cu[mt][nt], al[mt][0], al[mt][1], al[mt][2], al[mt][3], buh[nt][0], buh[nt][1]);
                }
            }
        }
        __syncthreads();
    }

    // ---- epilogue: swish-gate, write H as bf16 hi/lo pairs ----
    const float* bg_e = bg + e * M;
    const float* b1_e = b1 + e * M;
    uint32_t* Hh32 = (uint32_t*)g_H_hi;
    uint32_t* Hl32 = (uint32_t*)g_H_lo;
#pragma unroll
    for (int mt = 0; mt < 4; mt++) {
#pragma unroll
        for (int nt = 0; nt < 4; nt++) {
            int r_base = row0 + warp_m * 64 + mt * 16 + (lane >> 2);
            int c = col0 + warp_n * 32 + nt * 8 + (lane & 3) * 2;
#pragma unroll
            for (int hh = 0; hh < 2; hh++) {
                int r = r_base + hh * 8;
                if (r < cnt) {
                    float a0 = cg[mt][nt][2*hh]   + bg_e[c];
                    float a1 = cg[mt][nt][2*hh+1] + bg_e[c + 1];
                    float u0 = cu[mt][nt][2*hh]   + b1_e[c];
                    float u1 = cu[mt][nt][2*hh+1] + b1_e[c + 1];
                    float h0 = (a0 / (1.0f + __expf(-a0))) * u0;
                    float h1 = (a1 / (1.0f + __expf(-a1))) * u1;
                    uint32_t hu, lu;
                    split2(h0, h1, hu, lu);
                    size_t o = ((size_t)(base + r) * M + c) >> 1;
                    Hh32[o] = hu;
                    Hl32[o] = lu;
                }
            }
        }
    }
}

// ff2: stage = 4 planes (A hi/lo, B hi/lo), double buffered
#define F2_STG  (4 * TILEB)          // 40960
#define F2_SMEM (2 * F2_STG)         // 81920
#define SPLITK  4

__device__ __forceinline__ void ff2_load(uint32_t sb, int stage, int kabs,
                                         int tid, int base, int cnt,
                                         int row0, int e, int col0) {
    uint32_t st = sb + stage * F2_STG;
    int ch = tid & 3;
    // A: H hi/lo rows (invalid rows clamped; discarded in epilogue)
#pragma unroll
    for (int p = 0; p < 4; p++) {
        int r = (((p & 1) << 8) + tid) >> 2;
        const __nv_bfloat16* hs = (p >> 1) ? g_H_lo : g_H_hi;
        int gr = row0 + r;
        if (gr >= cnt) gr = cnt - 1;
        const void* src = hs + (size_t)(base + gr) * M + kabs + ch * 8;
        cpa16(st + (p >> 1) * TILEB + r * ROWB + ch * 16, src);
    }
    // B: W2 transposed planes [n=D][k=M]
#pragma unroll
    for (int p = 0; p < 4; p++) {
        int r = (((p & 1) << 8) + tid) >> 2;
        const __nv_bfloat16* ws = (p >> 1) ? g_W2t_lo : g_W2t_hi;
        const void* src = ws + ((size_t)e * D + col0 + r) * (size_t)M + kabs + ch * 8;
        cpa16(st + (2 + (p >> 1)) * TILEB + r * ROWB + ch * 16, src);
    }
}

// ---------------- kernel 5: ff2  Y = H@W2 + b2, weighted combine (split-K) ----
__global__ void __launch_bounds__(256)
k_ff2(const float* __restrict__ b2, float* __restrict__ out) {
    extern __shared__ char smem[];
    const int e = blockIdx.z >> 2;
    const int sk = blockIdx.z & 3;
    const int base = g_off[e];
    const int cnt = g_off[e + 1] - base;
    const int row0 = blockIdx.x * 128;
    if (row0 >= cnt) return;
    const int col0 = blockIdx.y * 128;
    const int kb = sk * (M / SPLITK);
    const int tid = threadIdx.x;
    const int wid = tid >> 5, lane = tid & 31;
    const int warp_m = wid >> 2, warp_n = wid & 3;
    const uint32_t sb = smem_u32(smem);

    const uint32_t a_rel = (uint32_t)(((warp_m * 64 + (lane & 15)) * AS + (lane >> 4) * 8) * 2);
    const uint32_t b_rel = (uint32_t)(((warp_n * 32 + (lane & 7) + ((lane >> 4) * 8)) * AS
                                      + ((lane >> 3) & 1) * 8) * 2);

    float cc[4][4][4];
#pragma unroll
    for (int i = 0; i < 4; i++)
#pragma unroll
        for (int j = 0; j < 4; j++)
#pragma unroll
            for (int q = 0; q < 4; q++) cc[i][j][q] = 0.0f;

    ff2_load(sb, 0, kb, tid, base, cnt, row0, e, col0);
    CPCOMMIT();

    const int NIT = (M / SPLITK) / 32;   // 32
    for (int it = 0; it < NIT; it++) {
        if (it + 1 < NIT) {
            ff2_load(sb, (it + 1) & 1, kb + (it + 1) * 32, tid, base, cnt, row0, e, col0);
            CPCOMMIT();
            CPWAIT(1);
        } else {
            CPWAIT(0);
        }
        __syncthreads();
        uint32_t st = sb + (it & 1) * F2_STG;
#pragma unroll
        for (int ks = 0; ks < 2; ks++) {
            const uint32_t kso = (uint32_t)(ks * 16 * 2);
            uint32_t ah[4][4], al[4][4];
#pragma unroll
            for (int mt = 0; mt < 4; mt++) {
                uint32_t ad = st + a_rel + (uint32_t)(mt * 16 * ROWB) + kso;
                LDSM4(ah[mt][0], ah[mt][1], ah[mt][2], ah[mt][3], ad);
                LDSM4(al[mt][0], al[mt][1], al[mt][2], al[mt][3], ad + TILEB);
            }
            uint32_t bh[4][2], bl[4][2];
#pragma unroll
            for (int nt2 = 0; nt2 < 2; nt2++) {
                uint32_t bd = st + b_rel + (uint32_t)(nt2 * 16 * ROWB) + kso;
                LDSM4(bh[2*nt2][0], bh[2*nt2][1], bh[2*nt2+1][0], bh[2*nt2+1][1], bd + 2 * TILEB);
                LDSM4(bl[2*nt2][0], bl[2*nt2][1], bl[2*nt2+1][0], bl[2*nt2+1][1], bd + 3 * TILEB);
            }
#pragma unroll
            for (int mt = 0; mt < 4; mt++) {
#pragma unroll
                for (int nt = 0; nt < 4; nt++) {
                    MMA16816(cc[mt][nt], ah[mt][0], ah[mt][1], ah[mt][2], ah[mt][3], bh[nt][0], bh[nt][1]);
                    MMA16816(cc[mt][nt], ah[mt][0], ah[mt][1], ah[mt][2], ah[mt][3], bl[nt][0], bl[nt][1]);
                    MMA16816(cc[mt][nt], al[mt][0], al[mt][1], al[mt][2], al[mt][3], bh[nt][0], bh[nt][1]);
                }
            }
        }
        __syncthreads();
    }

    // ---- epilogue: (bias on split 0) + weighted atomic combine ----
    const float* b2_e = b2 + e * D;
#pragma unroll
    for (int mt = 0; mt < 4; mt++) {
#pragma unroll
        for (int nt = 0; nt < 4; nt++) {
            int r_base = row0 + warp_m * 64 + mt * 16 + (lane >> 2);
            int c = col0 + warp_n * 32 + nt * 8 + (lane & 3) * 2;
            float bb0 = (sk == 0) ? b2_e[c]     : 0.0f;
            float bb1 = (sk == 0) ? b2_e[c + 1] : 0.0f;
#pragma unroll
            for (int hh = 0; hh < 2; hh++) {
                int r = r_base + hh * 8;
                if (r < cnt) {
                    int slot = base + r;
                    int tok = g_slot_tok[slot];
                    float w = g_slot_w[slot];
                    float y0 = cc[mt][nt][2*hh]   + bb0;
                    float y1 = cc[mt][nt][2*hh+1] + bb1;
                    float* op = out + (size_t)tok * D + c;
                    atomicAdd(op,     w * y0);
                    atomicAdd(op + 1, w * y1);
                }
            }
        }
    }
}

// ---------------- launch ----------------
extern "C" void kernel_launch(void* const* d_in, const int* in_sizes, int n_in,
                              void* d_out, int out_size) {
    const float* x     = (const float*)d_in[0];
    const float* Wgate = (const float*)d_in[1];
    const float* bgate = (const float*)d_in[2];
    const float* Wg    = (const float*)d_in[3];
    const float* bg    = (const float*)d_in[4];
    const float* W1    = (const float*)d_in[5];
    const float* b1    = (const float*)d_in[6];
    const float* W2    = (const float*)d_in[7];
    const float* b2    = (const float*)d_in[8];
    float* out = (float*)d_out;

    cudaFuncSetAttribute(k_ff1, cudaFuncAttributeMaxDynamicSharedMemorySize, F1_SMEM);
    cudaFuncSetAttribute(k_ff2, cudaFuncAttributeMaxDynamicSharedMemorySize, F2_SMEM);

    k_init<<<(S * D + 511) / 512, 512>>>(out);
    k_gate<<<S / 8, 256>>>(x, Wgate, bgate);
    k_offsets<<<1, 32>>>();
    k_scatter<<<(S + 255) / 256, 256>>>();

    // prep: bf16 hi/lo splits (+ weight transpose); plane selected device-side
    k_xsplit<<<(S * D / 2 + 255) / 256, 256>>>(x);
    dim3 tb(32, 8);
    k_tsplit<<<dim3(M / 32, D / 32, E), tb>>>(Wg, 0, D, M);
    k_tsplit<<<dim3(M / 32, D / 32, E), tb>>>(W1, 1, D, M);
    k_tsplit<<<dim3(D / 32, M / 32, E), tb>>>(W2, 2, M, D);

    dim3 g1(NSLOT / 128, M / 128, E);          // (32, 32, 8)
    k_ff1<<<g1, 256, F1_SMEM>>>(bg, b1);
    dim3 g2(NSLOT / 128, D / 128, E * SPLITK); // (32, 8, 32)
    k_ff2<<<g2, 256, F2_SMEM>>>(b2, out);
}

// round 11
// speedup vs baseline: 2.1305x; 1.0551x over previous
#include <cuda_runtime.h>
#include <cuda_bf16.h>
#include <math.h>
#include <stdint.h>

// Problem constants
#define S 2048
#define D 1024
#define E 8
#define M 4096
#define NSLOT (2*S)

// ---------------- device scratch (bf16 hi/lo planes) ----------------
__device__ __nv_bfloat16 g_x_hi[(size_t)S * D];
__device__ __nv_bfloat16 g_x_lo[(size_t)S * D];
__device__ __nv_bfloat16 g_Wgt_hi[(size_t)E * M * D];   // [e][n=M][k=D]
__device__ __nv_bfloat16 g_Wgt_lo[(size_t)E * M * D];
__device__ __nv_bfloat16 g_W1t_hi[(size_t)E * M * D];
__device__ __nv_bfloat16 g_W1t_lo[(size_t)E * M * D];
__device__ __nv_bfloat16 g_W2t_hi[(size_t)E * D * M];   // [e][n=D][k=M]
__device__ __nv_bfloat16 g_W2t_lo[(size_t)E * D * M];
__device__ __nv_bfloat16 g_H_hi[(size_t)NSLOT * M];
__device__ __nv_bfloat16 g_H_lo[(size_t)NSLOT * M];
__device__ int   g_cnt[E];
__device__ int   g_off[E + 1];
__device__ int   g_pos[E];
__device__ int   g_slot_tok[NSLOT];
__device__ float g_slot_w[NSLOT];
__device__ int   g_tok_e[S * 2];
__device__ float g_tok_w[S * 2];

// ---------------- helpers ----------------
__device__ __forceinline__ uint32_t smem_u32(const void* p) {
    uint32_t a;
    asm("{ .reg .u64 t; cvta.to.shared.u64 t, %1; cvt.u32.u64 %0, t; }" : "=r"(a) : "l"(p));
    return a;
}

#define LDSM4(r0, r1, r2, r3, addr) \
    asm volatile("ldmatrix.sync.aligned.m8n8.x4.shared.b16 {%0,%1,%2,%3}, [%4];" \
        : "=r"(r0), "=r"(r1), "=r"(r2), "=r"(r3) : "r"(addr))

#define MMA16816(c, a0, a1, a2, a3, b0, b1) \
    asm volatile("mma.sync.aligned.m16n8k16.row.col.f32.bf16.bf16.f32 " \
        "{%0,%1,%2,%3}, {%4,%5,%6,%7}, {%8,%9}, {%0,%1,%2,%3};" \
        : "+f"((c)[0]), "+f"((c)[1]), "+f"((c)[2]), "+f"((c)[3]) \
        : "r"(a0), "r"(a1), "r"(a2), "r"(a3), "r"(b0), "r"(b1))

// Plain 16B cp.async
__device__ __forceinline__ void cpa16(uint32_t dst, const void* src) {
    asm volatile("cp.async.cg.shared.global [%0], [%1], 16;"
                 :: "r"(dst), "l"(src));
}
#define CPCOMMIT() asm volatile("cp.async.commit_group;")
#define CPWAIT(n)  asm volatile("cp.async.wait_group %0;" :: "n"(n))

// Split fp32 pair -> packed bf16x2 hi and lo
__device__ __forceinline__ void split2(float a, float b, uint32_t& hi, uint32_t& lo) {
    __nv_bfloat16 ah = __float2bfloat16(a);
    __nv_bfloat16 bh = __float2bfloat16(b);
    __nv_bfloat162 h2; h2.x = ah; h2.y = bh;
    __nv_bfloat162 l2 = __floats2bfloat162_rn(a - __bfloat162float(ah),
                                              b - __bfloat162float(bh));
    hi = *(uint32_t*)&h2;
    lo = *(uint32_t*)&l2;
}

// ---------------- kernel 0: zero output + counters ----------------
__global__ void k_init(float* out) {
    int t = blockIdx.x * blockDim.x + threadIdx.x;
    if (t < S * D) out[t] = 0.0f;
    if (t < E) g_cnt[t] = 0;
}

// ---------------- kernel 1: gating (1 warp / token) ----------------
__global__ void k_gate(const float* __restrict__ x,
                       const float* __restrict__ Wgate,
                       const float* __restrict__ bgate) {
    int warp = (blockIdx.x * blockDim.x + threadIdx.x) >> 5;
    int lane = threadIdx.x & 31;
    if (warp >= S) return;
    const float* xr = x + (size_t)warp * D;
    float acc[E];
#pragma unroll
    for (int e = 0; e < E; e++) acc[e] = 0.0f;
    for (int d = lane; d < D; d += 32) {
        float xv = xr[d];
        const float* wr = Wgate + d * E;
#pragma unroll
        for (int e = 0; e < E; e++) acc[e] += xv * wr[e];
    }
#pragma unroll
    for (int e = 0; e < E; e++) {
#pragma unroll
        for (int o = 16; o > 0; o >>= 1)
            acc[e] += __shfl_down_sync(0xffffffffu, acc[e], o);
    }
    if (lane == 0) {
        float l[E];
        float mx = -1e30f;
#pragma unroll
        for (int e = 0; e < E; e++) { l[e] = acc[e] + bgate[e]; mx = fmaxf(mx, l[e]); }
        float ex[E];
#pragma unroll
        for (int e = 0; e < E; e++) ex[e] = expf(l[e] - mx);
        int i0 = 0;
#pragma unroll
        for (int e = 1; e < E; e++) if (ex[e] > ex[i0]) i0 = e;
        int i1 = (i0 == 0) ? 1 : 0;
#pragma unroll
        for (int e = 0; e < E; e++) if (e != i0 && ex[e] > ex[i1]) i1 = e;
        float w0 = ex[i0], w1 = ex[i1];
        float inv = 1.0f / (w0 + w1);
        w0 *= inv; w1 *= inv;
        g_tok_e[warp * 2 + 0] = i0; g_tok_w[warp * 2 + 0] = w0;
        g_tok_e[warp * 2 + 1] = i1; g_tok_w[warp * 2 + 1] = w1;
        atomicAdd(&g_cnt[i0], 1);
        atomicAdd(&g_cnt[i1], 1);
    }
}

// ---------------- kernel 2: prefix offsets ----------------
__global__ void k_offsets() {
    if (threadIdx.x == 0) {
        int acc = 0;
        g_off[0] = 0;
        for (int e = 0; e < E; e++) {
            acc += g_cnt[e];
            g_off[e + 1] = acc;
            g_pos[e] = g_off[e];
        }
    }
}

// ---------------- kernel 3: scatter ----------------
__global__ void k_scatter() {
    int t = blockIdx.x * blockDim.x + threadIdx.x;
    if (t >= S) return;
#pragma unroll
    for (int k = 0; k < 2; k++) {
        int e = g_tok_e[t * 2 + k];
        int p = atomicAdd(&g_pos[e], 1);
        g_slot_tok[p] = t;
        g_slot_w[p] = g_tok_w[t * 2 + k];
    }
}

// ---------------- prep: split x ----------------
__global__ void k_xsplit(const float* __restrict__ x) {
    int i = blockIdx.x * blockDim.x + threadIdx.x;
    if (i >= S * D / 2) return;
    float2 v = ((const float2*)x)[i];
    uint32_t h, l;
    split2(v.x, v.y, h, l);
    ((uint32_t*)g_x_hi)[i] = h;
    ((uint32_t*)g_x_lo)[i] = l;
}

// ---------------- prep: transpose + split weights  in[K][N] -> out[N][K] ----------
// Output plane selected IN DEVICE CODE (host-side __device__ symbol args are the
// host shadow address — the R7-R9 silent-zero bug). Coalesced u32 (bf16x2) writes.
__global__ void k_tsplit(const float* __restrict__ in, int which, int K, int N) {
    __nv_bfloat16 *oh, *ol;
    if (which == 0)      { oh = g_Wgt_hi; ol = g_Wgt_lo; }
    else if (which == 1) { oh = g_W1t_hi; ol = g_W1t_lo; }
    else                 { oh = g_W2t_hi; ol = g_W2t_lo; }
    __shared__ float t[64][33];
    const size_t eo = (size_t)blockIdx.z * K * N;
    in += eo;
    uint32_t* ohu = (uint32_t*)(oh + eo);
    uint32_t* olu = (uint32_t*)(ol + eo);
    int n0 = blockIdx.x * 32, k0 = blockIdx.y * 64;
    int tx = threadIdx.x, ty = threadIdx.y;   // (32, 8)
#pragma unroll
    for (int i = 0; i < 8; i++) {
        int kl = ty + 8 * i;
        t[kl][tx] = in[(size_t)(k0 + kl) * N + n0 + tx];
    }
    __syncthreads();
#pragma unroll
    for (int i = 0; i < 4; i++) {
        int nl = ty + 8 * i;
        float v0 = t[2 * tx][nl];
        float v1 = t[2 * tx + 1][nl];
        uint32_t h, l;
        split2(v0, v1, h, l);
        size_t o = ((size_t)(n0 + nl) * K + k0) / 2 + tx;
        ohu[o] = h;
        olu[o] = l;
    }
}

// ---------------- GEMM tiling ----------------
#define AS 72                        // smem row stride, bf16 elems (144 B)
#define ROWB (AS * 2)                // 144 (mod 128 = 16 -> conflict-free ldmatrix)
#define PLANEB (128 * ROWB)          // 18432 bytes per 128x64 plane

// ff1: stage = 6 planes (A hi/lo, G hi/lo, U hi/lo), double buffered, K-chunk 64
#define F1_STG  (6 * PLANEB)         // 110592
#define F1_SMEM (2 * F1_STG + 512)   // 221696

__device__ __forceinline__ void ff1_load(uint32_t sb, int stage, int k0,
                                         int tid, const int* s_tok,
                                         int e, int col0) {
    uint32_t st = sb + stage * F1_STG;
    // A: x hi/lo gathered rows. 1024 x 16B per plane, 4 per thread.
#pragma unroll
    for (int p = 0; p < 8; p++) {
        int idx = (p & 3) * 256 + tid;       // 0..1023
        int r = idx >> 3, c = idx & 7;       // row, 16B chunk
        const __nv_bfloat16* xs = (p >> 2) ? g_x_lo : g_x_hi;
        int tok = s_tok[r];
        if (tok < 0) tok = 0;
        const void* src = xs + (size_t)tok * D + k0 + c * 8;
        cpa16(st + (p >> 2) * PLANEB + r * ROWB + c * 16, src);
    }
    // B: Wg/W1 transposed planes [n][k]
#pragma unroll
    for (int p = 0; p < 16; p++) {
        int idx = (p & 3) * 256 + tid;
        int r = idx >> 3, c = idx & 7;
        int w = p >> 2;
        const __nv_bfloat16* ws = w == 0 ? g_Wgt_hi
                                : w == 1 ? g_Wgt_lo
                                : w == 2 ? g_W1t_hi : g_W1t_lo;
        const void* src = ws + ((size_t)e * M + col0 + r) * (size_t)D + k0 + c * 8;
        cpa16(st + (2 + w) * PLANEB + r * ROWB + c * 16, src);
    }
}

// ---------------- kernel 4: ff1  H = swish(X@Wg+bg) * (X@W1+b1) ----------------
__global__ void __launch_bounds__(256)
k_ff1(const float* __restrict__ bg, const float* __restrict__ b1) {
    extern __shared__ char smem[];
    const int e = blockIdx.z;
    const int base = g_off[e];
    const int cnt = g_off[e + 1] - base;
    const int row0 = blockIdx.x * 128;
    if (row0 >= cnt) return;
    const int col0 = blockIdx.y * 128;
    const int tid = threadIdx.x;
    const int wid = tid >> 5, lane = tid & 31;
    const int warp_m = wid >> 2, warp_n = wid & 3;
    const uint32_t sb = smem_u32(smem);

    int* s_tok = (int*)(smem + 2 * F1_STG);
    if (tid < 128) {
        int gr = row0 + tid;
        s_tok[tid] = (gr < cnt) ? g_slot_tok[base + gr] : -1;
    }
    __syncthreads();

    const uint32_t a_rel = (uint32_t)(((warp_m * 64 + (lane & 15)) * AS + (lane >> 4) * 8) * 2);
    const uint32_t b_rel = (uint32_t)(((warp_n * 32 + (lane & 7) + ((lane >> 4) * 8)) * AS
                                      + ((lane >> 3) & 1) * 8) * 2);

    float cg[4][4][4], cu[4][4][4];
#pragma unroll
    for (int i = 0; i < 4; i++)
#pragma unroll
        for (int j = 0; j < 4; j++)
#pragma unroll
            for (int q = 0; q < 4; q++) { cg[i][j][q] = 0.0f; cu[i][j][q] = 0.0f; }

    ff1_load(sb, 0, 0, tid, s_tok, e, col0);
    CPCOMMIT();

    const int NIT = D / 64;   // 16
    for (int it = 0; it < NIT; it++) {
        if (it + 1 < NIT) {
            ff1_load(sb, (it + 1) & 1, (it + 1) * 64, tid, s_tok, e, col0);
            CPCOMMIT();
            CPWAIT(1);
        } else {
            CPWAIT(0);
        }
        __syncthreads();
        uint32_t st = sb + (it & 1) * F1_STG;
#pragma unroll
        for (int ks = 0; ks < 4; ks++) {
            const uint32_t kso = (uint32_t)(ks * 32);   // 16 elems = 32 B per step
            uint32_t ah[4][4], al[4][4];
#pragma unroll
            for (int mt = 0; mt < 4; mt++) {
                uint32_t ad = st + a_rel + (uint32_t)(mt * 16 * ROWB) + kso;
                LDSM4(ah[mt][0], ah[mt][1], ah[mt][2], ah[mt][3], ad);
                LDSM4(al[mt][0], al[mt][1], al[mt][2], al[mt][3], ad + PLANEB);
            }
            uint32_t bgh[4][2], bgl[4][2], buh[4][2], bul[4][2];
#pragma unroll
            for (int nt2 = 0; nt2 < 2; nt2++) {
                uint32_t bd = st + b_rel + (uint32_t)(nt2 * 16 * ROWB) + kso;
                LDSM4(bgh[2*nt2][0], bgh[2*nt2][1], bgh[2*nt2+1][0], bgh[2*nt2+1][1], bd + 2 * PLANEB);
                LDSM4(bgl[2*nt2][0], bgl[2*nt2][1], bgl[2*nt2+1][0], bgl[2*nt2+1][1], bd + 3 * PLANEB);
                LDSM4(buh[2*nt2][0], buh[2*nt2][1], buh[2*nt2+1][0], buh[2*nt2+1][1], bd + 4 * PLANEB);
                LDSM4(bul[2*nt2][0], bul[2*nt2][1], bul[2*nt2+1][0], bul[2*nt2+1][1], bd + 5 * PLANEB);
            }
#pragma unroll
            for (int mt = 0; mt < 4; mt++) {
#pragma unroll
                for (int nt = 0; nt < 4; nt++) {
                    MMA16816(cg[mt][nt], ah[mt][0], ah[mt][1], ah[mt][2], ah[mt][3], bgh[nt][0], bgh[nt][1]);
                    MMA16816(cg[mt][nt], ah[mt][0], ah[mt][1], ah[mt][2], ah[mt][3], bgl[nt][0], bgl[nt][1]);
                    MMA16816(cg[mt][nt], al[mt][0], al[mt][1], al[mt][2], al[mt][3], bgh[nt][0], bgh[nt][1]);
                    MMA16816(cu[mt][nt], ah[mt][0], ah[mt][1], ah[mt][2], ah[mt][3], buh[nt][0], buh[nt][1]);
                    MMA16816(cu[mt][nt], ah[mt][0], ah[mt][1], ah[mt][2], ah[mt][3], bul[nt][0], bul[nt][1]);
                    MMA16816(cu[mt][nt], al[mt][0], al[mt][1], al[mt][2], al[mt][3], buh[nt][0], buh[nt][1]);
                }
            }
        }
        __syncthreads();
    }

    // ---- epilogue: swish-gate, write H as bf16 hi/lo pairs ----
    const float* bg_e = bg + e * M;
    const float* b1_e = b1 + e * M;
    uint32_t* Hh32 = (uint32_t*)g_H_hi;
    uint32_t* Hl32 = (uint32_t*)g_H_lo;
#pragma unroll
    for (int mt = 0; mt < 4; mt++) {
#pragma unroll
        for (int nt = 0; nt < 4; nt++) {
            int r_base = row0 + warp_m * 64 + mt * 16 + (lane >> 2);
            int c = col0 + warp_n * 32 + nt * 8 + (lane & 3) * 2;
#pragma unroll
            for (int hh = 0; hh < 2; hh++) {
                int r = r_base + hh * 8;
                if (r < cnt) {
                    float a0 = cg[mt][nt][2*hh]   + bg_e[c];
                    float a1 = cg[mt][nt][2*hh+1] + bg_e[c + 1];
                    float u0 = cu[mt][nt][2*hh]   + b1_e[c];
                    float u1 = cu[mt][nt][2*hh+1] + b1_e[c + 1];
                    float h0 = (a0 / (1.0f + __expf(-a0))) * u0;
                    float h1 = (a1 / (1.0f + __expf(-a1))) * u1;
                    uint32_t hu, lu;
                    split2(h0, h1, hu, lu);
                    size_t o = ((size_t)(base + r) * M + c) >> 1;
                    Hh32[o] = hu;
                    Hl32[o] = lu;
                }
            }
        }
    }
}

// ff2: stage = 4 planes (A hi/lo, B hi/lo), double buffered, K-chunk 64
#define F2_STG  (4 * PLANEB)          // 73728
#define F2_SMEM (2 * F2_STG)          // 147456
#define SPLITK  4

__device__ __forceinline__ void ff2_load(uint32_t sb, int stage, int kabs,
                                         int tid, int base, int cnt,
                                         int row0, int e, int col0) {
    uint32_t st = sb + stage * F2_STG;
    // A: H hi/lo rows (invalid rows clamped; discarded in epilogue)
#pragma unroll
    for (int p = 0; p < 8; p++) {
        int idx = (p & 3) * 256 + tid;
        int r = idx >> 3, c = idx & 7;
        const __nv_bfloat16* hs = (p >> 2) ? g_H_lo : g_H_hi;
        int gr = row0 + r;
        if (gr >= cnt) gr = cnt - 1;
        const void* src = hs + (size_t)(base + gr) * M + kabs + c * 8;
        cpa16(st + (p >> 2) * PLANEB + r * ROWB + c * 16, src);
    }
    // B: W2 transposed planes [n=D][k=M]
#pragma unroll
    for (int p = 0; p < 8; p++) {
        int idx = (p & 3) * 256 + tid;
        int r = idx >> 3, c = idx & 7;
        const __nv_bfloat16* ws = (p >> 2) ? g_W2t_lo : g_W2t_hi;
        const void* src = ws + ((size_t)e * D + col0 + r) * (size_t)M + kabs + c * 8;
        cpa16(st + (2 + (p >> 2)) * PLANEB + r * ROWB + c * 16, src);
    }
}

// ---------------- kernel 5: ff2  Y = H@W2 + b2, weighted combine (split-K) ----
__global__ void __launch_bounds__(256)
k_ff2(const float* __restrict__ b2, float* __restrict__ out) {
    extern __shared__ char smem[];
    const int e = blockIdx.z >> 2;
    const int sk = blockIdx.z & 3;
    const int base = g_off[e];
    const int cnt = g_off[e + 1] - base;
    const int row0 = blockIdx.x * 128;
    if (row0 >= cnt) return;
    const int col0 = blockIdx.y * 128;
    const int kb = sk * (M / SPLITK);
    const int tid = threadIdx.x;
    const int wid = tid >> 5, lane = tid & 31;
    const int warp_m = wid >> 2, warp_n = wid & 3;
    const uint32_t sb = smem_u32(smem);

    const uint32_t a_rel = (uint32_t)(((warp_m * 64 + (lane & 15)) * AS + (lane >> 4) * 8) * 2);
    const uint32_t b_rel = (uint32_t)(((warp_n * 32 + (lane & 7) + ((lane >> 4) * 8)) * AS
                                      + ((lane >> 3) & 1) * 8) * 2);

    float cc[4][4][4];
#pragma unroll
    for (int i = 0; i < 4; i++)
#pragma unroll
        for (int j = 0; j < 4; j++)
#pragma unroll
            for (int q = 0; q < 4; q++) cc[i][j][q] = 0.0f;

    ff2_load(sb, 0, kb, tid, base, cnt, row0, e, col0);
    CPCOMMIT();

    const int NIT = (M / SPLITK) / 64;   // 16
    for (int it = 0; it < NIT; it++) {
        if (it + 1 < NIT) {
            ff2_load(sb, (it + 1) & 1, kb + (it + 1) * 64, tid, base, cnt, row0, e, col0);
            CPCOMMIT();
            CPWAIT(1);
        } else {
            CPWAIT(0);
        }
        __syncthreads();
        uint32_t st = sb + (it & 1) * F2_STG;
#pragma unroll
        for (int ks = 0; ks < 4; ks++) {
            const uint32_t kso = (uint32_t)(ks * 32);
            uint32_t ah[4][4], al[4][4];
#pragma unroll
            for (int mt = 0; mt < 4; mt++) {
                uint32_t ad = st + a_rel + (uint32_t)(mt * 16 * ROWB) + kso;
                LDSM4(ah[mt][0], ah[mt][1], ah[mt][2], ah[mt][3], ad);
                LDSM4(al[mt][0], al[mt][1], al[mt][2], al[mt][3], ad + PLANEB);
            }
            uint32_t bh[4][2], bl[4][2];
#pragma unroll
            for (int nt2 = 0; nt2 < 2; nt2++) {
                uint32_t bd = st + b_rel + (uint32_t)(nt2 * 16 * ROWB) + kso;
                LDSM4(bh[2*nt2][0], bh[2*nt2][1], bh[2*nt2+1][0], bh[2*nt2+1][1], bd + 2 * PLANEB);
                LDSM4(bl[2*nt2][0], bl[2*nt2][1], bl[2*nt2+1][0], bl[2*nt2+1][1], bd + 3 * PLANEB);
            }
#pragma unroll
            for (int mt = 0; mt < 4; mt++) {
#pragma unroll
                for (int nt = 0; nt < 4; nt++) {
                    MMA16816(cc[mt][nt], ah[mt][0], ah[mt][1], ah[mt][2], ah[mt][3], bh[nt][0], bh[nt][1]);
                    MMA16816(cc[mt][nt], ah[mt][0], ah[mt][1], ah[mt][2], ah[mt][3], bl[nt][0], bl[nt][1]);
                    MMA16816(cc[mt][nt], al[mt][0], al[mt][1], al[mt][2], al[mt][3], bh[nt][0], bh[nt][1]);
                }
            }
        }
        __syncthreads();
    }

    // ---- epilogue: (bias on split 0) + weighted atomic combine ----
    const float* b2_e = b2 + e * D;
#pragma unroll
    for (int mt = 0; mt < 4; mt++) {
#pragma unroll
        for (int nt = 0; nt < 4; nt++) {
            int r_base = row0 + warp_m * 64 + mt * 16 + (lane >> 2);
            int c = col0 + warp_n * 32 + nt * 8 + (lane & 3) * 2;
            float bb0 = (sk == 0) ? b2_e[c]     : 0.0f;
            float bb1 = (sk == 0) ? b2_e[c + 1] : 0.0f;
#pragma unroll
            for (int hh = 0; hh < 2; hh++) {
                int r = r_base + hh * 8;
                if (r < cnt) {
                    int slot = base + r;
                    int tok = g_slot_tok[slot];
                    float w = g_slot_w[slot];
                    float y0 = cc[mt][nt][2*hh]   + bb0;
                    float y1 = cc[mt][nt][2*hh+1] + bb1;
                    float* op = out + (size_t)tok * D + c;
                    atomicAdd(op,     w * y0);
                    atomicAdd(op + 1, w * y1);
                }
            }
        }
    }
}

// ---------------- launch ----------------
extern "C" void kernel_launch(void* const* d_in, const int* in_sizes, int n_in,
                              void* d_out, int out_size) {
    const float* x     = (const float*)d_in[0];
    const float* Wgate = (const float*)d_in[1];
    const float* bgate = (const float*)d_in[2];
    const float* Wg    = (const float*)d_in[3];
    const float* bg    = (const float*)d_in[4];
    const float* W1    = (const float*)d_in[5];
    const float* b1    = (const float*)d_in[6];
    const float* W2    = (const float*)d_in[7];
    const float* b2    = (const float*)d_in[8];
    float* out = (float*)d_out;

    cudaFuncSetAttribute(k_ff1, cudaFuncAttributeMaxDynamicSharedMemorySize, F1_SMEM);
    cudaFuncSetAttribute(k_ff2, cudaFuncAttributeMaxDynamicSharedMemorySize, F2_SMEM);

    k_init<<<(S * D + 511) / 512, 512>>>(out);
    k_gate<<<S / 8, 256>>>(x, Wgate, bgate);
    k_offsets<<<1, 32>>>();
    k_scatter<<<(S + 255) / 256, 256>>>();

    // prep: bf16 hi/lo splits (+ weight transpose); plane selected device-side
    k_xsplit<<<(S * D / 2 + 255) / 256, 256>>>(x);
    dim3 tb(32, 8);
    k_tsplit<<<dim3(M / 32, D / 64, E), tb>>>(Wg, 0, D, M);
    k_tsplit<<<dim3(M / 32, D / 64, E), tb>>>(W1, 1, D, M);
    k_tsplit<<<dim3(D / 32, M / 64, E), tb>>>(W2, 2, M, D);

    dim3 g1(NSLOT / 128, M / 128, E);          // (32, 32, 8)
    k_ff1<<<g1, 256, F1_SMEM>>>(bg, b1);
    dim3 g2(NSLOT / 128, D / 128, E * SPLITK); // (32, 8, 32)
    k_ff2<<<g2, 256, F2_SMEM>>>(b2, out);
}